// round 11
// baseline (speedup 1.0000x reference)
#include <cuda_runtime.h>
#include <math.h>

#define Bk 64
#define Sk 1024
#define Ck 512
#define Vk 140
#define Ak 512
#define Hk 512
#define Tk 128
#define GATES 2048   // 4*H
#define INW 652      // V + A
#define NCHUNK 32    // S chunks per batch (32 rows each)
#define KSPLIT 8     // gates K splits
#define NBLK 148     // persistent grid: <= SM count, 1 block/SM (smem-limited)
#define NVB  296     // 2 virtual blocks per block
#define VSMF 16512   // floats of smem per virtual block

// ---------------- device state (static allocation only) ----------------
__device__ float g_keys[(size_t)Bk * Sk * Ak];     // 134 MB
__device__ float g_h[Bk * Hk];
__device__ float g_c[2][Bk * Hk];                  // parity double buffer
__device__ float g_q[Bk * Ak];
__device__ float g_ctx[Bk * Ak];
__device__ float g_gp[KSPLIT][Bk * GATES];         // gates partials
__device__ float g_pm[Bk * NCHUNK];
__device__ float g_pl[Bk * NCHUNK];
__device__ float g_pctx[(size_t)Bk * NCHUNK * Ak];
__device__ float g_logits[Bk * Vk];
__device__ int   g_cnt[Bk];
__device__ int   g_idx[Bk];
__device__ int           g_bar_cnt;
__device__ volatile int  g_bar_gen;

__device__ __forceinline__ float sigmf(float x) { return 1.f / (1.f + expf(-x)); }

// virtual-block barrier: 256 threads, named barrier id 1 or 2
__device__ __forceinline__ void vb_sync(int sb) {
    asm volatile("bar.sync %0, 256;" :: "r"(sb) : "memory");
}

// grid-wide barrier (all NBLK blocks resident: grid <= SM count, smem
// caps occupancy at 1 block/SM)
__device__ __forceinline__ void grid_sync() {
    __syncthreads();
    if (threadIdx.x == 0) {
        __threadfence();
        int gen = g_bar_gen;                 // read BEFORE arrive
        int prev = atomicAdd(&g_bar_cnt, 1);
        if (prev == NBLK - 1) {
            g_bar_cnt = 0;
            __threadfence();
            g_bar_gen = gen + 1;
        } else {
            while (g_bar_gen == gen) { __nanosleep(32); }
        }
        __threadfence();
    }
    __syncthreads();
}

// ---------------- init ---------------------------------------------------
__global__ void init_kernel(const int* __restrict__ labels,
                            const float* __restrict__ Hc_b) {
    int b = blockIdx.x, tid = threadIdx.x;
    g_h[b * Hk + tid] = 0.f;
    g_c[0][b * Hk + tid] = 0.f;
    g_q[b * Ak + tid] = Hc_b[tid];
    if (tid == 0) { g_idx[b] = labels[b * Tk]; g_cnt[b] = 0; }
}

// ---------------- keys = X @ Ic_w^T + Ic_b  (once) ------------------------
__global__ void keys_gemm(const float* __restrict__ X,
                          const float* __restrict__ W,
                          const float* __restrict__ bias) {
    const int bs0 = blockIdx.x * 64;
    const int a0  = blockIdx.y * 64;
    const int tid = threadIdx.x;
    const int tx = tid & 15, ty = tid >> 4;
    __shared__ float Xs[64][33];
    __shared__ float Ws[64][33];
    float acc[4][4] = {};
    for (int k0 = 0; k0 < Ck; k0 += 32) {
        for (int idx = tid; idx < 64 * 32; idx += 256) {
            int r = idx >> 5, kk = idx & 31;
            Xs[r][kk] = X[(size_t)(bs0 + r) * Ck + k0 + kk];
            Ws[r][kk] = W[(size_t)(a0 + r) * Ck + k0 + kk];
        }
        __syncthreads();
#pragma unroll
        for (int kk = 0; kk < 32; kk++) {
            float xr[4], wc[4];
#pragma unroll
            for (int i = 0; i < 4; i++) xr[i] = Xs[ty * 4 + i][kk];
#pragma unroll
            for (int j = 0; j < 4; j++) wc[j] = Ws[tx * 4 + j][kk];
#pragma unroll
            for (int i = 0; i < 4; i++)
#pragma unroll
                for (int j = 0; j < 4; j++) acc[i][j] += xr[i] * wc[j];
        }
        __syncthreads();
    }
#pragma unroll
    for (int i = 0; i < 4; i++)
#pragma unroll
        for (int j = 0; j < 4; j++)
            g_keys[(size_t)(bs0 + ty * 4 + i) * Ak + a0 + tx * 4 + j] =
                acc[i][j] + bias[a0 + tx * 4 + j];
}

// ---------------- persistent mega kernel ----------------------------------
__global__ __launch_bounds__(512, 1)
void mega_kernel(const float* __restrict__ W_ih, const float* __restrict__ b_ih,
                 const float* __restrict__ W_hh, const float* __restrict__ b_hh,
                 const float* __restrict__ Wout, const float* __restrict__ b_out,
                 const float* __restrict__ Hc_w, const float* __restrict__ Hc_b,
                 float* __restrict__ out) {
    extern __shared__ float smraw[];
    const int hb   = threadIdx.x >> 8;   // which virtual block (0/1)
    const int tid  = threadIdx.x & 255;  // tid within virtual block
    const int sb   = hb + 1;             // named barrier id
    float* vsm = smraw + hb * VSMF;
    const int vb = blockIdx.x * 2 + hb;  // 0..295
    const int lane = tid & 31;
    const int w = tid >> 5;

    for (int t = 0; t < Tk; t++) {
        // ====== Phase A: argmax(prev) + attention partials + fused merge ==
        {
            float* keys_s = vsm;             // [32][512]
            float* scores = vsm + 16384;     // [32]
            float* p_s    = vsm + 16416;     // [32]
            float* facs   = vsm + 16448;     // [32]
            float* lg     = vsm + 16480;     // [1]
            int*   aflag  = (int*)(vsm + 16481);

            // argmax of step t-1 logits (one warp; first-occurrence)
            if (vb < Bk && t > 0 && w == 0) {
                const int b = vb;
                float best = -1e30f; int bi = 0;
                for (int v = lane; v < Vk; v += 32) {
                    float lv = __ldcg(&g_logits[b * Vk + v]);
                    if (lv > best) { best = lv; bi = v; }
                }
#pragma unroll
                for (int o = 16; o; o >>= 1) {
                    float ov = __shfl_xor_sync(0xffffffffu, best, o);
                    int   oi = __shfl_xor_sync(0xffffffffu, bi,  o);
                    if (ov > best || (ov == best && oi < bi)) { best = ov; bi = oi; }
                }
                if (lane == 0) __stcg(&g_idx[b], bi);
            }

            for (int task = vb; task < Bk * NCHUNK; task += NVB) {
                const int b = task >> 5, chunk = task & 31;
                // q in registers (L2 resident)
                const float4* qg = (const float4*)(g_q + b * Ak);
                const float4 qv0 = __ldcg(&qg[lane]);
                const float4 qv1 = __ldcg(&qg[32 + lane]);
                const float4 qv2 = __ldcg(&qg[64 + lane]);
                const float4 qv3 = __ldcg(&qg[96 + lane]);
                const float* kb = g_keys + ((size_t)b * Sk + chunk * 32) * Ak;
#pragma unroll
                for (int i = 0; i < 4; i++) {
                    const int row = w * 4 + i;
                    const float4* src = (const float4*)(kb + (size_t)row * Ak);
                    float4 k0 = src[lane], k1 = src[32 + lane],
                           k2 = src[64 + lane], k3 = src[96 + lane];
                    float4* dst = (float4*)(keys_s + row * Ak);
                    dst[lane] = k0; dst[32 + lane] = k1;
                    dst[64 + lane] = k2; dst[96 + lane] = k3;
                    float d = k0.x*qv0.x + k0.y*qv0.y + k0.z*qv0.z + k0.w*qv0.w
                            + k1.x*qv1.x + k1.y*qv1.y + k1.z*qv1.z + k1.w*qv1.w
                            + k2.x*qv2.x + k2.y*qv2.y + k2.z*qv2.z + k2.w*qv2.w
                            + k3.x*qv3.x + k3.y*qv3.y + k3.z*qv3.z + k3.w*qv3.w;
#pragma unroll
                    for (int o = 16; o; o >>= 1)
                        d += __shfl_xor_sync(0xffffffffu, d, o);
                    if (lane == 0) scores[row] = d * 0.04419417382415922f;
                }
                vb_sync(sb);
                // softmax stats by warp 0 only
                if (w == 0) {
                    float s_l = scores[lane];
                    float M = s_l;
#pragma unroll
                    for (int o = 16; o; o >>= 1)
                        M = fmaxf(M, __shfl_xor_sync(0xffffffffu, M, o));
                    float p_l = expf(s_l - M);
                    float L = p_l;
#pragma unroll
                    for (int o = 16; o; o >>= 1)
                        L += __shfl_xor_sync(0xffffffffu, L, o);
                    p_s[lane] = p_l;
                    if (lane == 0) {
                        __stcg(&g_pm[task], M);
                        __stcg(&g_pl[task], L);
                    }
                }
                vb_sync(sb);
                // pass C: warp w owns A-cols [w*64, w*64+64); lane owns 2
                const int c0 = w * 64 + lane * 2;
                float acc0 = 0.f, acc1 = 0.f;
#pragma unroll
                for (int r = 0; r < 32; r++) {
                    const float p = p_s[r];
                    const float2 kv = *(const float2*)(keys_s + r * Ak + c0);
                    acc0 += p * kv.x;
                    acc1 += p * kv.y;
                }
                float2 o2; o2.x = acc0; o2.y = acc1;
                __stcg((float2*)&g_pctx[(size_t)task * Ak + c0], o2);

                // fused merge: release-fence, then elect last arriver for b
                __threadfence();
                vb_sync(sb);
                if (tid == 0) {
                    int prev = atomicAdd(&g_cnt[b], 1);
                    aflag[0] = (prev == NCHUNK - 1) ? 1 : 0;
                }
                vb_sync(sb);
                if (aflag[0]) {
                    __threadfence();
                    if (w == 0) {
                        float pm_l = __ldcg(&g_pm[b * NCHUNK + lane]);
                        float pl_l = __ldcg(&g_pl[b * NCHUNK + lane]);
                        float Mg = pm_l;
#pragma unroll
                        for (int o = 16; o; o >>= 1)
                            Mg = fmaxf(Mg, __shfl_xor_sync(0xffffffffu, Mg, o));
                        float fl = expf(pm_l - Mg);
                        float Ll = fl * pl_l;
#pragma unroll
                        for (int o = 16; o; o >>= 1)
                            Ll += __shfl_xor_sync(0xffffffffu, Ll, o);
                        facs[lane] = fl;
                        if (lane == 0) lg[0] = Ll;
                    }
                    vb_sync(sb);
                    const float invL = 1.f / lg[0];
#pragma unroll
                    for (int r2 = 0; r2 < 2; r2++) {
                        int a = tid + r2 * 256;
                        float s = 0.f;
#pragma unroll
                        for (int c = 0; c < NCHUNK; c++)
                            s += facs[c] *
                                 __ldcg(&g_pctx[(size_t)(b * NCHUNK + c) * Ak + a]);
                        __stcg(&g_ctx[b * Ak + a], s * invL);
                    }
                    if (tid == 0) __stcg(&g_cnt[b], 0);
                }
            }
        }
        grid_sync();

        // ================= Phase G: gates (split-K x8) ====================
        if (vb < 256) {
            const int ks = vb & 7;
            const int rowTile = vb >> 3;
            const int tx = tid & 15;   // batch group
            const int ty = tid >> 4;   // row group
            float* Wt = vsm;           // [64][33]
            float* Xt = vsm + 2112;    // [64][33]
            float acc[4][4] = {};
            const int row0 = rowTile * 64;
            const int kbase = ks * 128;
            for (int k0 = 0; k0 < 128; k0 += 32) {
                for (int idx = tid; idx < 64 * 32; idx += 256) {
                    int r = idx >> 5, kk = idx & 31;
                    int kg = kbase + k0 + kk;
                    int row = row0 + r;
                    Wt[r * 33 + kk] = (kg < 512)
                        ? W_ih[(size_t)row * INW + Vk + kg]
                        : W_hh[(size_t)row * Hk + kg - 512];
                }
                for (int idx = tid; idx < 64 * 32; idx += 256) {
                    int r = idx >> 5, kk = idx & 31;
                    int kg = kbase + k0 + kk;
                    Xt[r * 33 + kk] = (kg < 512)
                        ? __ldcg(&g_ctx[r * Ak + kg])
                        : __ldcg(&g_h[r * Hk + kg - 512]);
                }
                vb_sync(sb);
#pragma unroll
                for (int kk = 0; kk < 32; kk++) {
                    float wv[4], xv[4];
#pragma unroll
                    for (int i = 0; i < 4; i++) wv[i] = Wt[(ty * 4 + i) * 33 + kk];
#pragma unroll
                    for (int j = 0; j < 4; j++) xv[j] = Xt[(tx * 4 + j) * 33 + kk];
#pragma unroll
                    for (int i = 0; i < 4; i++)
#pragma unroll
                        for (int j = 0; j < 4; j++) acc[i][j] += wv[i] * xv[j];
                }
                vb_sync(sb);
            }
#pragma unroll
            for (int i = 0; i < 4; i++) {
                const int row = row0 + ty * 4 + i;
                float extra = 0.f;
                if (ks == 0) extra = b_ih[row] + b_hh[row];
#pragma unroll
                for (int j = 0; j < 4; j++) {
                    const int bb = tx * 4 + j;
                    float v = acc[i][j] + extra;
                    if (ks == 0)
                        v += W_ih[(size_t)row * INW + __ldcg(&g_idx[bb])];
                    __stcg(&g_gp[ks][bb * GATES + row], v);
                }
            }
        }
        grid_sync();

        // ========= Phase F: pointwise + logits + qproj (4 slices/b) =======
        if (vb < 256) {
            const int b = vb >> 2;
            const int slice = vb & 3;
            const int p = t & 1;
            float* h_s = vsm;  // [512]
#pragma unroll
            for (int r = 0; r < 2; r++) {
                int jj = tid + r * 256;
                float gi = 0.f, gf = 0.f, gg = 0.f, go = 0.f;
#pragma unroll
                for (int pp = 0; pp < KSPLIT; pp++) {
                    const float* gp = g_gp[pp] + b * GATES;
                    gi += __ldcg(&gp[jj]);
                    gf += __ldcg(&gp[512 + jj]);
                    gg += __ldcg(&gp[1024 + jj]);
                    go += __ldcg(&gp[1536 + jj]);
                }
                float cprev = __ldcg(&g_c[p][b * Hk + jj]);
                float cn = sigmf(gf) * cprev + sigmf(gi) * tanhf(gg);
                float hn = sigmf(go) * tanhf(cn);
                if (slice == 0) {
                    __stcg(&g_c[1 - p][b * Hk + jj], cn);
                    __stcg(&g_h[b * Hk + jj], hn);
                }
                h_s[jj] = hn;
            }
            vb_sync(sb);
            const float4* h4 = (const float4*)h_s;
            const float4 hv0 = h4[lane], hv1 = h4[32 + lane],
                         hv2 = h4[64 + lane], hv3 = h4[96 + lane];
            // logits rows [slice*35, slice*35+35)
            for (int vi = w; vi < 35; vi += 8) {
                const int v = slice * 35 + vi;
                const float4* wr = (const float4*)(Wout + (size_t)v * Hk);
                float4 w0 = wr[lane], w1 = wr[32 + lane],
                       w2 = wr[64 + lane], w3 = wr[96 + lane];
                float s = w0.x*hv0.x + w0.y*hv0.y + w0.z*hv0.z + w0.w*hv0.w
                        + w1.x*hv1.x + w1.y*hv1.y + w1.z*hv1.z + w1.w*hv1.w
                        + w2.x*hv2.x + w2.y*hv2.y + w2.z*hv2.z + w2.w*hv2.w
                        + w3.x*hv3.x + w3.y*hv3.y + w3.z*hv3.z + w3.w*hv3.w;
#pragma unroll
                for (int o = 16; o; o >>= 1)
                    s += __shfl_xor_sync(0xffffffffu, s, o);
                if (lane == 0) {
                    float lv = s + b_out[v];
                    __stcg(&g_logits[b * Vk + v], lv);
                    out[((size_t)b * Tk + t) * Vk + v] = lv;
                }
            }
            // qproj rows [slice*128, slice*128+128)
#pragma unroll
            for (int g = 0; g < 4; g++) {
                const int r0 = slice * 128 + w * 16 + g * 4;
                float s[4];
#pragma unroll
                for (int k = 0; k < 4; k++) {
                    const float4* wr = (const float4*)(Hc_w + (size_t)(r0 + k) * Hk);
                    float4 w0 = wr[lane], w1 = wr[32 + lane],
                           w2 = wr[64 + lane], w3 = wr[96 + lane];
                    s[k] = w0.x*hv0.x + w0.y*hv0.y + w0.z*hv0.z + w0.w*hv0.w
                         + w1.x*hv1.x + w1.y*hv1.y + w1.z*hv1.z + w1.w*hv1.w
                         + w2.x*hv2.x + w2.y*hv2.y + w2.z*hv2.z + w2.w*hv2.w
                         + w3.x*hv3.x + w3.y*hv3.y + w3.z*hv3.z + w3.w*hv3.w;
                }
#pragma unroll
                for (int k = 0; k < 4; k++) {
#pragma unroll
                    for (int o = 16; o; o >>= 1)
                        s[k] += __shfl_xor_sync(0xffffffffu, s[k], o);
                }
                if (lane < 4)
                    __stcg(&g_q[b * Ak + r0 + lane], s[lane] + Hc_b[r0 + lane]);
            }
        }
        grid_sync();
    }
}

// ---------------- launch --------------------------------------------------
extern "C" void kernel_launch(void* const* d_in, const int* in_sizes, int n_in,
                              void* d_out, int out_size) {
    const float* image  = (const float*)d_in[0];
    const int*   labels = (const int*)d_in[1];
    const float* Ic_w   = (const float*)d_in[2];
    const float* Ic_b   = (const float*)d_in[3];
    const float* Hc_w   = (const float*)d_in[4];
    const float* Hc_b   = (const float*)d_in[5];
    const float* W_ih   = (const float*)d_in[6];
    const float* b_ih   = (const float*)d_in[7];
    const float* W_hh   = (const float*)d_in[8];
    const float* b_hh   = (const float*)d_in[9];
    const float* Wout   = (const float*)d_in[10];
    const float* b_out  = (const float*)d_in[11];
    float* out = (float*)d_out;

    const int smem_mega = 2 * VSMF * 4;  // 132096 bytes -> 1 block/SM
    cudaFuncSetAttribute(mega_kernel,
                         cudaFuncAttributeMaxDynamicSharedMemorySize,
                         smem_mega);

    init_kernel<<<Bk, 512>>>(labels, Hc_b);
    keys_gemm<<<dim3((Bk * Sk) / 64, Ak / 64), 256>>>(image, Ic_w, Ic_b);
    mega_kernel<<<NBLK, 512, smem_mega>>>(W_ih, b_ih, W_hh, b_hh,
                                          Wout, b_out, Hc_w, Hc_b, out);
}

// round 12
// speedup vs baseline: 1.0483x; 1.0483x over previous
#include <cuda_runtime.h>
#include <math.h>

#define Bk 64
#define Sk 1024
#define Ck 512
#define Vk 140
#define Ak 512
#define Hk 512
#define Tk 128
#define GATES 2048   // 4*H
#define INW 652      // V + A
#define NCHUNK 32    // S chunks per batch (32 rows each)
#define KSPLIT 8     // gates K splits
#define NBLK 148     // persistent grid: <= SM count, 1 block/SM (smem-limited)
#define NVB  296     // 2 virtual blocks per block
#define VSMGF 4224   // floats of smem per virtual block for G/F/M phases
#define SMEMF (32768 + 64)  // total dynamic smem floats (phase A dominates)

// ---------------- device state (static allocation only) ----------------
__device__ float g_keys[(size_t)Bk * Sk * Ak];     // 134 MB
__device__ float g_h[Bk * Hk];
__device__ float g_c[2][Bk * Hk];                  // parity double buffer
__device__ float g_q[Bk * Ak];
__device__ float g_ctx[Bk * Ak];
__device__ float g_gp[KSPLIT][Bk * GATES];         // gates partials
__device__ float g_pm[Bk * NCHUNK];
__device__ float g_pl[Bk * NCHUNK];
__device__ float g_pctx[(size_t)Bk * NCHUNK * Ak];
__device__ float g_logits[Bk * Vk];
__device__ int   g_idx[Bk];
__device__ int           g_bar_cnt;
__device__ volatile int  g_bar_gen;

__device__ __forceinline__ float sigmf(float x) { return 1.f / (1.f + expf(-x)); }

__device__ __forceinline__ void cp16(void* dst, const void* src) {
    unsigned d = (unsigned)__cvta_generic_to_shared(dst);
    asm volatile("cp.async.cg.shared.global [%0], [%1], 16;"
                 :: "r"(d), "l"(src) : "memory");
}
__device__ __forceinline__ void cp_commit() {
    asm volatile("cp.async.commit_group;" ::: "memory");
}
template <int N>
__device__ __forceinline__ void cp_wait() {
    asm volatile("cp.async.wait_group %0;" :: "n"(N) : "memory");
}

// virtual-block barrier: 256 threads, named barrier id 1 or 2
__device__ __forceinline__ void vb_sync(int sb) {
    asm volatile("bar.sync %0, 256;" :: "r"(sb) : "memory");
}

// grid-wide barrier (all NBLK blocks resident: grid <= SM count, smem
// caps occupancy at 1 block/SM)
__device__ __forceinline__ void grid_sync() {
    __syncthreads();
    if (threadIdx.x == 0) {
        __threadfence();
        int gen = g_bar_gen;                 // read BEFORE arrive
        int prev = atomicAdd(&g_bar_cnt, 1);
        if (prev == NBLK - 1) {
            g_bar_cnt = 0;
            __threadfence();
            g_bar_gen = gen + 1;
        } else {
            while (g_bar_gen == gen) { __nanosleep(32); }
        }
        __threadfence();
    }
    __syncthreads();
}

// ---------------- init ---------------------------------------------------
__global__ void init_kernel(const int* __restrict__ labels,
                            const float* __restrict__ Hc_b) {
    int b = blockIdx.x, tid = threadIdx.x;
    g_h[b * Hk + tid] = 0.f;
    g_c[0][b * Hk + tid] = 0.f;
    g_q[b * Ak + tid] = Hc_b[tid];
    if (tid == 0) g_idx[b] = labels[b * Tk];
}

// ---------------- keys = X @ Ic_w^T + Ic_b  (once) ------------------------
__global__ void keys_gemm(const float* __restrict__ X,
                          const float* __restrict__ W,
                          const float* __restrict__ bias) {
    const int bs0 = blockIdx.x * 64;
    const int a0  = blockIdx.y * 64;
    const int tid = threadIdx.x;
    const int tx = tid & 15, ty = tid >> 4;
    __shared__ float Xs[64][33];
    __shared__ float Ws[64][33];
    float acc[4][4] = {};
    for (int k0 = 0; k0 < Ck; k0 += 32) {
        for (int idx = tid; idx < 64 * 32; idx += 256) {
            int r = idx >> 5, kk = idx & 31;
            Xs[r][kk] = X[(size_t)(bs0 + r) * Ck + k0 + kk];
            Ws[r][kk] = W[(size_t)(a0 + r) * Ck + k0 + kk];
        }
        __syncthreads();
#pragma unroll
        for (int kk = 0; kk < 32; kk++) {
            float xr[4], wc[4];
#pragma unroll
            for (int i = 0; i < 4; i++) xr[i] = Xs[ty * 4 + i][kk];
#pragma unroll
            for (int j = 0; j < 4; j++) wc[j] = Ws[tx * 4 + j][kk];
#pragma unroll
            for (int i = 0; i < 4; i++)
#pragma unroll
                for (int j = 0; j < 4; j++) acc[i][j] += xr[i] * wc[j];
        }
        __syncthreads();
    }
#pragma unroll
    for (int i = 0; i < 4; i++)
#pragma unroll
        for (int j = 0; j < 4; j++)
            g_keys[(size_t)(bs0 + ty * 4 + i) * Ak + a0 + tx * 4 + j] =
                acc[i][j] + bias[a0 + tx * 4 + j];
}

// ---------------- persistent mega kernel ----------------------------------
__global__ __launch_bounds__(512, 1)
void mega_kernel(const float* __restrict__ W_ih, const float* __restrict__ b_ih,
                 const float* __restrict__ W_hh, const float* __restrict__ b_hh,
                 const float* __restrict__ Wout, const float* __restrict__ b_out,
                 const float* __restrict__ Hc_w, const float* __restrict__ Hc_b,
                 float* __restrict__ out) {
    extern __shared__ float smraw[];
    const int tidx = threadIdx.x;        // 0..511 (phase A uses full block)
    const int hb   = tidx >> 8;          // virtual block (0/1) for M/G/F
    const int tid  = tidx & 255;         // tid within virtual block
    const int sb   = hb + 1;             // named barrier id
    float* vsm = smraw + hb * VSMGF;     // per-vblock scratch for M/G/F
    const int vb = blockIdx.x * 2 + hb;  // 0..295
    const int lane = tidx & 31;
    const int wfull = tidx >> 5;         // warp id in full block (0..15)
    const int w = tid >> 5;              // warp id in vblock (0..7)
    const int bx = blockIdx.x;

    // phase A smem layout (full block)
    float* bufA   = smraw;               // [2][16384]
    float* scores = smraw + 32768;       // [32]
    float* p_s    = smraw + 32800;       // [32]

    const int ntask = (Bk * NCHUNK - bx + NBLK - 1) / NBLK;

    for (int t = 0; t < Tk; t++) {
        // ====== Phase A: argmax(prev) + attention partials (cp.async) =====
        {
            // argmax of step t-1 logits (blocks 0..63, warp 0)
            if (bx < Bk && t > 0 && wfull == 0) {
                const int b = bx;
                float best = -1e30f; int bi = 0;
                for (int v = lane; v < Vk; v += 32) {
                    float lv = __ldcg(&g_logits[b * Vk + v]);
                    if (lv > best) { best = lv; bi = v; }
                }
#pragma unroll
                for (int o = 16; o; o >>= 1) {
                    float ov = __shfl_xor_sync(0xffffffffu, best, o);
                    int   oi = __shfl_xor_sync(0xffffffffu, bi,  o);
                    if (ov > best || (ov == best && oi < bi)) { best = ov; bi = oi; }
                }
                if (lane == 0) __stcg(&g_idx[b], bi);
            }

            // preload task 0 into buffer 0
            {
                const int task0 = bx;
                const float* kb = g_keys +
                    ((size_t)(task0 >> 5) * Sk + (task0 & 31) * 32) * Ak;
#pragma unroll
                for (int j = 0; j < 8; j++) {
                    int e = (j * 512 + tidx) * 4;
                    cp16(bufA + e, kb + e);
                }
                cp_commit();
            }

            for (int i = 0; i < ntask; i++) {
                const int task = bx + i * NBLK;
                const int b = task >> 5;
                // issue next tile into the other buffer
                if (i + 1 < ntask) {
                    const int nt = bx + (i + 1) * NBLK;
                    const float* kb2 = g_keys +
                        ((size_t)(nt >> 5) * Sk + (nt & 31) * 32) * Ak;
                    float* nb = bufA + ((i + 1) & 1) * 16384;
#pragma unroll
                    for (int j = 0; j < 8; j++) {
                        int e = (j * 512 + tidx) * 4;
                        cp16(nb + e, kb2 + e);
                    }
                    cp_commit();
                    cp_wait<1>();
                } else {
                    cp_wait<0>();
                }
                __syncthreads();
                float* cur = bufA + (i & 1) * 16384;

                // scores: warp wfull owns rows {2*wfull, 2*wfull+1}
                const float4* qg = (const float4*)(g_q + b * Ak);
                const float4 qv0 = __ldcg(&qg[lane]);
                const float4 qv1 = __ldcg(&qg[32 + lane]);
                const float4 qv2 = __ldcg(&qg[64 + lane]);
                const float4 qv3 = __ldcg(&qg[96 + lane]);
#pragma unroll
                for (int r = 0; r < 2; r++) {
                    const int row = wfull * 2 + r;
                    const float4* kr = (const float4*)(cur + row * Ak);
                    float4 k0 = kr[lane], k1 = kr[32 + lane],
                           k2 = kr[64 + lane], k3 = kr[96 + lane];
                    float d = k0.x*qv0.x + k0.y*qv0.y + k0.z*qv0.z + k0.w*qv0.w
                            + k1.x*qv1.x + k1.y*qv1.y + k1.z*qv1.z + k1.w*qv1.w
                            + k2.x*qv2.x + k2.y*qv2.y + k2.z*qv2.z + k2.w*qv2.w
                            + k3.x*qv3.x + k3.y*qv3.y + k3.z*qv3.z + k3.w*qv3.w;
#pragma unroll
                    for (int o = 16; o; o >>= 1)
                        d += __shfl_xor_sync(0xffffffffu, d, o);
                    if (lane == 0) scores[row] = d * 0.04419417382415922f;
                }
                __syncthreads();
                // block softmax stats (warp 0)
                if (wfull == 0) {
                    float s_l = scores[lane];
                    float M = s_l;
#pragma unroll
                    for (int o = 16; o; o >>= 1)
                        M = fmaxf(M, __shfl_xor_sync(0xffffffffu, M, o));
                    float p_l = expf(s_l - M);
                    float L = p_l;
#pragma unroll
                    for (int o = 16; o; o >>= 1)
                        L += __shfl_xor_sync(0xffffffffu, L, o);
                    p_s[lane] = p_l;
                    if (lane == 0) {
                        __stcg(&g_pm[task], M);
                        __stcg(&g_pl[task], L);
                    }
                }
                __syncthreads();
                // ctx partial: thread owns A-col tidx, fixed r order
                float acc = 0.f;
#pragma unroll
                for (int r = 0; r < 32; r++)
                    acc += p_s[r] * cur[r * Ak + tidx];
                __stcg(&g_pctx[(size_t)task * Ak + tidx], acc);
                __syncthreads();
            }
        }
        grid_sync();

        // ========== Phase M: merge 32 partials per batch ==================
        if (vb < 64) {
            const int b = vb;
            float* facs = vsm;          // [32]
            float* lg   = vsm + 32;     // [1]
            if (w == 0) {
                float pm_l = __ldcg(&g_pm[b * NCHUNK + lane]);
                float pl_l = __ldcg(&g_pl[b * NCHUNK + lane]);
                float Mg = pm_l;
#pragma unroll
                for (int o = 16; o; o >>= 1)
                    Mg = fmaxf(Mg, __shfl_xor_sync(0xffffffffu, Mg, o));
                float fl = expf(pm_l - Mg);
                float Ll = fl * pl_l;
#pragma unroll
                for (int o = 16; o; o >>= 1)
                    Ll += __shfl_xor_sync(0xffffffffu, Ll, o);
                facs[lane] = fl;
                if (lane == 0) lg[0] = Ll;
            }
            vb_sync(sb);
            const float invL = 1.f / lg[0];
#pragma unroll
            for (int r2 = 0; r2 < 2; r2++) {
                int a = tid + r2 * 256;
                float s = 0.f;
#pragma unroll
                for (int c = 0; c < NCHUNK; c++)
                    s += facs[c] *
                         __ldcg(&g_pctx[(size_t)(b * NCHUNK + c) * Ak + a]);
                __stcg(&g_ctx[b * Ak + a], s * invL);
            }
        }
        grid_sync();

        // ================= Phase G: gates (split-K x8) ====================
        if (vb < 256) {
            const int ks = vb & 7;
            const int rowTile = vb >> 3;
            const int tx = tid & 15;   // batch group
            const int ty = tid >> 4;   // row group
            float* Wt = vsm;           // [64][33]
            float* Xt = vsm + 2112;    // [64][33]
            float acc[4][4] = {};
            const int row0 = rowTile * 64;
            const int kbase = ks * 128;
            for (int k0 = 0; k0 < 128; k0 += 32) {
                for (int idx = tid; idx < 64 * 32; idx += 256) {
                    int r = idx >> 5, kk = idx & 31;
                    int kg = kbase + k0 + kk;
                    int row = row0 + r;
                    Wt[r * 33 + kk] = (kg < 512)
                        ? W_ih[(size_t)row * INW + Vk + kg]
                        : W_hh[(size_t)row * Hk + kg - 512];
                }
                for (int idx = tid; idx < 64 * 32; idx += 256) {
                    int r = idx >> 5, kk = idx & 31;
                    int kg = kbase + k0 + kk;
                    Xt[r * 33 + kk] = (kg < 512)
                        ? __ldcg(&g_ctx[r * Ak + kg])
                        : __ldcg(&g_h[r * Hk + kg - 512]);
                }
                vb_sync(sb);
#pragma unroll
                for (int kk = 0; kk < 32; kk++) {
                    float wv[4], xv[4];
#pragma unroll
                    for (int i = 0; i < 4; i++) wv[i] = Wt[(ty * 4 + i) * 33 + kk];
#pragma unroll
                    for (int j = 0; j < 4; j++) xv[j] = Xt[(tx * 4 + j) * 33 + kk];
#pragma unroll
                    for (int i = 0; i < 4; i++)
#pragma unroll
                        for (int j = 0; j < 4; j++) acc[i][j] += wv[i] * xv[j];
                }
                vb_sync(sb);
            }
#pragma unroll
            for (int i = 0; i < 4; i++) {
                const int row = row0 + ty * 4 + i;
                float extra = 0.f;
                if (ks == 0) extra = b_ih[row] + b_hh[row];
#pragma unroll
                for (int j = 0; j < 4; j++) {
                    const int bb = tx * 4 + j;
                    float v = acc[i][j] + extra;
                    if (ks == 0)
                        v += W_ih[(size_t)row * INW + __ldcg(&g_idx[bb])];
                    __stcg(&g_gp[ks][bb * GATES + row], v);
                }
            }
        }
        grid_sync();

        // ========= Phase F: pointwise + logits + qproj (4 slices/b) =======
        if (vb < 256) {
            const int b = vb >> 2;
            const int slice = vb & 3;
            const int p = t & 1;
            float* h_s = vsm;  // [512]
#pragma unroll
            for (int r = 0; r < 2; r++) {
                int jj = tid + r * 256;
                float gi = 0.f, gf = 0.f, gg = 0.f, go = 0.f;
#pragma unroll
                for (int pp = 0; pp < KSPLIT; pp++) {
                    const float* gp = g_gp[pp] + b * GATES;
                    gi += __ldcg(&gp[jj]);
                    gf += __ldcg(&gp[512 + jj]);
                    gg += __ldcg(&gp[1024 + jj]);
                    go += __ldcg(&gp[1536 + jj]);
                }
                float cprev = __ldcg(&g_c[p][b * Hk + jj]);
                float cn = sigmf(gf) * cprev + sigmf(gi) * tanhf(gg);
                float hn = sigmf(go) * tanhf(cn);
                if (slice == 0) {
                    __stcg(&g_c[1 - p][b * Hk + jj], cn);
                    __stcg(&g_h[b * Hk + jj], hn);
                }
                h_s[jj] = hn;
            }
            vb_sync(sb);
            const float4* h4 = (const float4*)h_s;
            const float4 hv0 = h4[lane], hv1 = h4[32 + lane],
                         hv2 = h4[64 + lane], hv3 = h4[96 + lane];
            // logits rows [slice*35, slice*35+35)
            for (int vi = w; vi < 35; vi += 8) {
                const int v = slice * 35 + vi;
                const float4* wr = (const float4*)(Wout + (size_t)v * Hk);
                float4 w0 = wr[lane], w1 = wr[32 + lane],
                       w2 = wr[64 + lane], w3 = wr[96 + lane];
                float s = w0.x*hv0.x + w0.y*hv0.y + w0.z*hv0.z + w0.w*hv0.w
                        + w1.x*hv1.x + w1.y*hv1.y + w1.z*hv1.z + w1.w*hv1.w
                        + w2.x*hv2.x + w2.y*hv2.y + w2.z*hv2.z + w2.w*hv2.w
                        + w3.x*hv3.x + w3.y*hv3.y + w3.z*hv3.z + w3.w*hv3.w;
#pragma unroll
                for (int o = 16; o; o >>= 1)
                    s += __shfl_xor_sync(0xffffffffu, s, o);
                if (lane == 0) {
                    float lv = s + b_out[v];
                    __stcg(&g_logits[b * Vk + v], lv);
                    out[((size_t)b * Tk + t) * Vk + v] = lv;
                }
            }
            // qproj rows [slice*128, slice*128+128)
#pragma unroll
            for (int g = 0; g < 4; g++) {
                const int r0 = slice * 128 + w * 16 + g * 4;
                float s[4];
#pragma unroll
                for (int k = 0; k < 4; k++) {
                    const float4* wr = (const float4*)(Hc_w + (size_t)(r0 + k) * Hk);
                    float4 w0 = wr[lane], w1 = wr[32 + lane],
                           w2 = wr[64 + lane], w3 = wr[96 + lane];
                    s[k] = w0.x*hv0.x + w0.y*hv0.y + w0.z*hv0.z + w0.w*hv0.w
                         + w1.x*hv1.x + w1.y*hv1.y + w1.z*hv1.z + w1.w*hv1.w
                         + w2.x*hv2.x + w2.y*hv2.y + w2.z*hv2.z + w2.w*hv2.w
                         + w3.x*hv3.x + w3.y*hv3.y + w3.z*hv3.z + w3.w*hv3.w;
                }
#pragma unroll
                for (int k = 0; k < 4; k++) {
#pragma unroll
                    for (int o = 16; o; o >>= 1)
                        s[k] += __shfl_xor_sync(0xffffffffu, s[k], o);
                }
                if (lane < 4)
                    __stcg(&g_q[b * Ak + r0 + lane], s[lane] + Hc_b[r0 + lane]);
            }
        }
        grid_sync();
    }
}

// ---------------- launch --------------------------------------------------
extern "C" void kernel_launch(void* const* d_in, const int* in_sizes, int n_in,
                              void* d_out, int out_size) {
    const float* image  = (const float*)d_in[0];
    const int*   labels = (const int*)d_in[1];
    const float* Ic_w   = (const float*)d_in[2];
    const float* Ic_b   = (const float*)d_in[3];
    const float* Hc_w   = (const float*)d_in[4];
    const float* Hc_b   = (const float*)d_in[5];
    const float* W_ih   = (const float*)d_in[6];
    const float* b_ih   = (const float*)d_in[7];
    const float* W_hh   = (const float*)d_in[8];
    const float* b_hh   = (const float*)d_in[9];
    const float* Wout   = (const float*)d_in[10];
    const float* b_out  = (const float*)d_in[11];
    float* out = (float*)d_out;

    const int smem_mega = SMEMF * 4;  // 131328 bytes -> 1 block/SM
    cudaFuncSetAttribute(mega_kernel,
                         cudaFuncAttributeMaxDynamicSharedMemorySize,
                         smem_mega);

    init_kernel<<<Bk, 512>>>(labels, Hc_b);
    keys_gemm<<<dim3((Bk * Sk) / 64, Ak / 64), 256>>>(image, Ic_w, Ic_b);
    mega_kernel<<<NBLK, 512, smem_mega>>>(W_ih, b_ih, W_hh, b_hh,
                                          Wout, b_out, Hc_w, Hc_b, out);
}